// round 14
// baseline (speedup 1.0000x reference)
#include <cuda_runtime.h>
#include <cuda_bf16.h>
#include <cuda_fp16.h>
#include <cstdint>

#define N_TOK 8192
#define DIM   64
#define BM    64
#define BN    128
#define HALF_KV 4096
#define NITER (HALF_KV / BN)   // 32

// ---------------- global scratch ----------------
__device__ __nv_bfloat16 g_Qh[N_TOK * DIM], g_Ql[N_TOK * DIM];
__device__ __nv_bfloat16 g_Kh[N_TOK * DIM], g_Kl[N_TOK * DIM];
__device__ __half g_Xt[DIM * N_TOK];
__device__ float g_Opart[2][N_TOK * DIM];
__device__ float g_mpart[2][N_TOK];
__device__ float g_lpart[2][N_TOK];

// ---------------- helpers ----------------
__device__ __forceinline__ uint32_t smem_u32(const void* p) {
    uint32_t a;
    asm("{ .reg .u64 t; cvta.to.shared.u64 t, %1; cvt.u32.u64 %0, t; }" : "=r"(a) : "l"(p));
    return a;
}
__device__ __forceinline__ uint32_t swz8(uint32_t row, uint32_t ch) {
    return row * 128u + ((ch ^ (row & 7u)) << 4);
}
__device__ __forceinline__ uint32_t swz16(uint32_t row, uint32_t ch) {
    return row * 256u + ((ch ^ (row & 7u)) << 4);
}
__device__ __forceinline__ void ldsm4(uint32_t& r0, uint32_t& r1, uint32_t& r2,
                                      uint32_t& r3, uint32_t addr) {
    asm volatile("ldmatrix.sync.aligned.m8n8.x4.shared.b16 {%0,%1,%2,%3}, [%4];"
                 : "=r"(r0), "=r"(r1), "=r"(r2), "=r"(r3) : "r"(addr));
}
__device__ __forceinline__ void mma16816(float* c, const uint32_t* a, uint32_t b0,
                                         uint32_t b1) {
    asm volatile(
        "mma.sync.aligned.m16n8k16.row.col.f32.bf16.bf16.f32 "
        "{%0,%1,%2,%3}, {%4,%5,%6,%7}, {%8,%9}, {%0,%1,%2,%3};"
        : "+f"(c[0]), "+f"(c[1]), "+f"(c[2]), "+f"(c[3])
        : "r"(a[0]), "r"(a[1]), "r"(a[2]), "r"(a[3]), "r"(b0), "r"(b1));
}
__device__ __forceinline__ void mma16816h(float* c, const uint32_t* a, uint32_t b0,
                                          uint32_t b1) {
    asm volatile(
        "mma.sync.aligned.m16n8k16.row.col.f32.f16.f16.f32 "
        "{%0,%1,%2,%3}, {%4,%5,%6,%7}, {%8,%9}, {%0,%1,%2,%3};"
        : "+f"(c[0]), "+f"(c[1]), "+f"(c[2]), "+f"(c[3])
        : "r"(a[0]), "r"(a[1]), "r"(a[2]), "r"(a[3]), "r"(b0), "r"(b1));
}
__device__ __forceinline__ uint32_t cvt2h(float lo, float hi) {
    uint32_t r;
    asm("cvt.rn.f16x2.f32 %0, %1, %2;" : "=r"(r) : "f"(hi), "f"(lo));
    return r;
}
__device__ __forceinline__ uint32_t ex2h2(uint32_t v) {
    uint32_t r;
    asm("ex2.approx.f16x2 %0, %1;" : "=r"(r) : "r"(v));
    return r;
}
// packed bf16x2 convert + split (proven in R7/R8)
__device__ __forceinline__ uint32_t cvt2bf(float lo, float hi) {
    uint32_t r;
    asm("cvt.rn.bf16x2.f32 %0, %1, %2;" : "=r"(r) : "f"(hi), "f"(lo));
    return r;
}
__device__ __forceinline__ void splitbf2(float a, float b, uint32_t& hi, uint32_t& lo) {
    hi = cvt2bf(a, b);
    float fa = __uint_as_float(hi << 16);
    float fb = __uint_as_float(hi & 0xFFFF0000u);
    lo = cvt2bf(a - fa, b - fb);
}
__device__ __forceinline__ void cpa16(uint32_t dst, const void* src) {
    asm volatile("cp.async.cg.shared.global [%0], [%1], 16;" :: "r"(dst), "l"(src));
}
#define CP_COMMIT() asm volatile("cp.async.commit_group;" ::: "memory")
#define CP_WAIT(n)  asm volatile("cp.async.wait_group %0;" :: "n"(n) : "memory")
#define ONES_H2 0x3C003C00u

// Q pre-scale: log2(e) / sqrt(64)  -> logits in log2 domain
#define QSCALE 0.18033688011112042f

// ---------------- tensor-core projection kernel ----------------
// 128 CTAs x 64 rows, 128 threads. smem: fp32 staging + split/transposed operands.
#define PT_ST   0                       // 64*65 fp32 = 16640 B
#define PT_RHT  16640
#define PT_RLT  (PT_RHT + 8192)
#define PT_EHT  (PT_RLT + 8192)
#define PT_ELT  (PT_EHT + 8192)
#define PT_XH   (PT_ELT + 8192)
#define PT_XL   (PT_XH + 8192)
#define PT_SMEM (PT_XL + 8192)          // 65,792 B

__global__ __launch_bounds__(128) void proj_tc(const float* __restrict__ x,
                                               const float* __restrict__ R,
                                               const float* __restrict__ E) {
    extern __shared__ char sm[];
    float* ST = (float*)(sm + PT_ST);
    uint32_t sb = smem_u32(sm);
    const int tid = threadIdx.x;
    const int lane = tid & 31;
    const int w = tid >> 5;
    const int m0 = w * 16;
    const int row0 = blockIdx.x * 64;
    const int g = lane >> 3, rr = lane & 7;

    // ---- stage R then E; build transposed split B operands [n][k] ----
#pragma unroll
    for (int rep = 0; rep < 2; rep++) {
        const float* src = rep ? E : R;
        uint32_t dh = rep ? PT_EHT : PT_RHT;
        uint32_t dl = rep ? PT_ELT : PT_RLT;
        __syncthreads();    // staging buffer free
#pragma unroll
        for (int i = tid; i < 1024; i += 128) {
            float4 v = ((const float4*)src)[i];
            int k = i >> 4, n4 = (i & 15) * 4;
            ST[k * 65 + n4]     = v.x;
            ST[k * 65 + n4 + 1] = v.y;
            ST[k * 65 + n4 + 2] = v.z;
            ST[k * 65 + n4 + 3] = v.w;
        }
        __syncthreads();
#pragma unroll
        for (int i = tid; i < 4096; i += 128) {
            int n = i >> 6, k = i & 63;
            float val = ST[k * 65 + n];      // B[n][k] = R[k][n]
            __nv_bfloat16 h = __float2bfloat16(val);
            uint32_t off = swz8((uint32_t)n, (uint32_t)(k >> 3)) + (k & 7) * 2;
            *(__nv_bfloat16*)(sm + dh + off) = h;
            *(__nv_bfloat16*)(sm + dl + off) = __float2bfloat16(val - __bfloat162float(h));
        }
    }

    // ---- stage x tile; Xt fp16 store + split A operand [m][k] ----
    __syncthreads();
#pragma unroll
    for (int i = tid; i < 1024; i += 128) {
        float4 v = ((const float4*)(x + (size_t)row0 * 64))[i];
        int r = i >> 4, c4 = (i & 15) * 4;
        ST[r * 65 + c4]     = v.x;
        ST[r * 65 + c4 + 1] = v.y;
        ST[r * 65 + c4 + 2] = v.z;
        ST[r * 65 + c4 + 3] = v.w;
    }
    __syncthreads();
#pragma unroll
    for (int i = tid; i < 4096; i += 128) {
        int d = i >> 6, r = i & 63;
        g_Xt[(size_t)d * N_TOK + row0 + r] = __float2half_rn(ST[r * 65 + d]);
    }
#pragma unroll
    for (int i = tid; i < 4096; i += 128) {
        int m = i >> 6, k = i & 63;
        float val = ST[m * 65 + k];
        __nv_bfloat16 h = __float2bfloat16(val);
        uint32_t off = swz8((uint32_t)m, (uint32_t)(k >> 3)) + (k & 7) * 2;
        *(__nv_bfloat16*)(sm + PT_XH + off) = h;
        *(__nv_bfloat16*)(sm + PT_XL + off) = __float2bfloat16(val - __bfloat162float(h));
    }
    __syncthreads();

    // ---- A fragments (x hi/lo), identical mapping to attn Q load ----
    uint32_t ah[4][4], al[4][4];
    {
        int arow = m0 + ((g & 1) << 3) + rr;
#pragma unroll
        for (int ks = 0; ks < 4; ks++) {
            uint32_t off = swz8(arow, ks * 2 + (g >> 1));
            ldsm4(ah[ks][0], ah[ks][1], ah[ks][2], ah[ks][3], sb + PT_XH + off);
            ldsm4(al[ks][0], al[ks][1], al[ks][2], al[ks][3], sb + PT_XL + off);
        }
    }

    // ---- 3-pass MMAs: Q = x@R, K = x@E ----
    float sq[8][4], sk[8][4];
#pragma unroll
    for (int t = 0; t < 8; t++)
#pragma unroll
        for (int j = 0; j < 4; j++) { sq[t][j] = 0.f; sk[t][j] = 0.f; }
#pragma unroll
    for (int np = 0; np < 4; np++) {
        int brow = np * 16 + ((g >> 1) << 3) + rr;
#pragma unroll
        for (int ks = 0; ks < 4; ks++) {
            uint32_t off = swz8(brow, ks * 2 + (g & 1));
            uint32_t r0, r1, r2, r3, l0, l1, l2, l3;
            uint32_t e0, e1, e2, e3, f0, f1, f2, f3;
            ldsm4(r0, r1, r2, r3, sb + PT_RHT + off);
            ldsm4(l0, l1, l2, l3, sb + PT_RLT + off);
            ldsm4(e0, e1, e2, e3, sb + PT_EHT + off);
            ldsm4(f0, f1, f2, f3, sb + PT_ELT + off);
            mma16816(sq[2 * np],     ah[ks], r0, r1);
            mma16816(sq[2 * np + 1], ah[ks], r2, r3);
            mma16816(sq[2 * np],     ah[ks], l0, l1);
            mma16816(sq[2 * np + 1], ah[ks], l2, l3);
            mma16816(sq[2 * np],     al[ks], r0, r1);
            mma16816(sq[2 * np + 1], al[ks], r2, r3);
            mma16816(sk[2 * np],     ah[ks], e0, e1);
            mma16816(sk[2 * np + 1], ah[ks], e2, e3);
            mma16816(sk[2 * np],     ah[ks], f0, f1);
            mma16816(sk[2 * np + 1], ah[ks], f2, f3);
            mma16816(sk[2 * np],     al[ks], e0, e1);
            mma16816(sk[2 * np + 1], al[ks], e2, e3);
        }
    }

    // ---- epilogue: scale Q, split to bf16 pairs, packed u32 stores ----
    {
        int q = lane >> 2;
        int cb = (lane & 3) * 2;
        int r_lo = row0 + m0 + q;
        int r_hi = r_lo + 8;
#pragma unroll
        for (int t = 0; t < 8; t++) {
            int col = t * 8 + cb;
            uint32_t hi, lo;
            splitbf2(sq[t][0] * QSCALE, sq[t][1] * QSCALE, hi, lo);
            *(uint32_t*)(g_Qh + (size_t)r_lo * 64 + col) = hi;
            *(uint32_t*)(g_Ql + (size_t)r_lo * 64 + col) = lo;
            splitbf2(sq[t][2] * QSCALE, sq[t][3] * QSCALE, hi, lo);
            *(uint32_t*)(g_Qh + (size_t)r_hi * 64 + col) = hi;
            *(uint32_t*)(g_Ql + (size_t)r_hi * 64 + col) = lo;
            splitbf2(sk[t][0], sk[t][1], hi, lo);
            *(uint32_t*)(g_Kh + (size_t)r_lo * 64 + col) = hi;
            *(uint32_t*)(g_Kl + (size_t)r_lo * 64 + col) = lo;
            splitbf2(sk[t][2], sk[t][3], hi, lo);
            *(uint32_t*)(g_Kh + (size_t)r_hi * 64 + col) = hi;
            *(uint32_t*)(g_Kl + (size_t)r_hi * 64 + col) = lo;
        }
    }
}

// ---------------- fused flash attention (identical to R13) ----------------
#define OFF_KH0 0
#define OFF_KL0 16384
#define OFF_KH1 32768
#define OFF_KL1 49152
#define OFF_X   65536
#define SMEM_TOTAL 81920

__global__ __launch_bounds__(128, 2) void attn_kernel() {
    extern __shared__ char sm[];
    uint32_t sb = smem_u32(sm);
    const int tid = threadIdx.x;
    const int lane = tid & 31;
    const int w = tid >> 5;
    const int m0 = w * 16;
    const int rb = blockIdx.x >> 1;
    const int half = blockIdx.x & 1;
    const int row0 = rb * BM;
    const int jb0 = half * HALF_KV;
    const int g = lane >> 3, rr = lane & 7;

#pragma unroll
    for (int i = tid; i < 64 * 8; i += 128) {
        int row = i >> 3, ch = i & 7;
        uint32_t sw = swz8(row, ch);
        *(uint4*)(sm + OFF_X + sw) = *(const uint4*)(g_Qh + (size_t)(row0 + row) * DIM + ch * 8);
        *(uint4*)(sm + OFF_X + 8192 + sw) = *(const uint4*)(g_Ql + (size_t)(row0 + row) * DIM + ch * 8);
    }
    __syncthreads();

    uint32_t qh[4][4], ql[4][4];
    {
        int arow = m0 + ((g & 1) << 3) + rr;
#pragma unroll
        for (int ks = 0; ks < 4; ks++) {
            uint32_t off = swz8(arow, ks * 2 + (g >> 1));
            ldsm4(qh[ks][0], qh[ks][1], qh[ks][2], qh[ks][3], sb + OFF_X + off);
            ldsm4(ql[ks][0], ql[ks][1], ql[ks][2], ql[ks][3], sb + OFF_X + 8192 + off);
        }
    }
    __syncthreads();

#pragma unroll
    for (int i = tid; i < 128 * 8; i += 128) {
        int row = i >> 3, ch = i & 7;
        uint32_t sw = swz8(row, ch);
        cpa16(sb + OFF_KH0 + sw, g_Kh + (size_t)(jb0 + row) * DIM + ch * 8);
        cpa16(sb + OFF_KL0 + sw, g_Kl + (size_t)(jb0 + row) * DIM + ch * 8);
    }
    CP_COMMIT();

    float o[8][4];
#pragma unroll
    for (int t = 0; t < 8; t++)
#pragma unroll
        for (int j = 0; j < 4; j++) o[t][j] = 0.f;
    float os[4];
#pragma unroll
    for (int j = 0; j < 4; j++) os[j] = 0.f;
    float mc0 = -3.0e38f, mc1 = -3.0e38f;

    for (int it = 0; it < NITER; it++) {
        int jb = jb0 + it * BN;
        __syncthreads();

#pragma unroll
        for (int i = tid; i < 64 * 16; i += 128) {
            int row = i >> 4, ch = i & 15;
            uint32_t sw = swz16(row, ch);
            cpa16(sb + OFF_X + sw, g_Xt + (size_t)row * N_TOK + jb + ch * 8);
        }
        CP_COMMIT();
        if (it + 1 < NITER) {
            uint32_t kb_h = ((it + 1) & 1) ? OFF_KH1 : OFF_KH0;
            uint32_t kb_l = ((it + 1) & 1) ? OFF_KL1 : OFF_KL0;
            int jn = jb + BN;
#pragma unroll
            for (int i = tid; i < 128 * 8; i += 128) {
                int row = i >> 3, ch = i & 7;
                uint32_t sw = swz8(row, ch);
                cpa16(sb + kb_h + sw, g_Kh + (size_t)(jn + row) * DIM + ch * 8);
                cpa16(sb + kb_l + sw, g_Kl + (size_t)(jn + row) * DIM + ch * 8);
            }
            CP_COMMIT();
            CP_WAIT(2);
        } else {
            CP_WAIT(1);
        }
        __syncthreads();

        uint32_t kh_b = (it & 1) ? OFF_KH1 : OFF_KH0;
        uint32_t kl_b = (it & 1) ? OFF_KL1 : OFF_KL0;

        float s[16][4];
#pragma unroll
        for (int t = 0; t < 16; t++)
#pragma unroll
            for (int j = 0; j < 4; j++) s[t][j] = 0.f;
#pragma unroll
        for (int np = 0; np < 8; np++) {
            int brow = np * 16 + ((g >> 1) << 3) + rr;
#pragma unroll
            for (int ks = 0; ks < 4; ks++) {
                uint32_t off = swz8(brow, ks * 2 + (g & 1));
                uint32_t b0, b1, b2, b3, c0, c1, c2, c3;
                ldsm4(b0, b1, b2, b3, sb + kh_b + off);
                ldsm4(c0, c1, c2, c3, sb + kl_b + off);
                mma16816(s[2 * np],     qh[ks], b0, b1);
                mma16816(s[2 * np + 1], qh[ks], b2, b3);
                mma16816(s[2 * np],     qh[ks], c0, c1);
                mma16816(s[2 * np + 1], qh[ks], c2, c3);
                mma16816(s[2 * np],     ql[ks], b0, b1);
                mma16816(s[2 * np + 1], ql[ks], b2, b3);
            }
        }

        if (it + 1 < NITER) { CP_WAIT(1); } else { CP_WAIT(0); }
        __syncthreads();

        float mx0 = -3.0e38f, mx1 = -3.0e38f;
#pragma unroll
        for (int t = 0; t < 16; t++) {
            mx0 = fmaxf(mx0, fmaxf(s[t][0], s[t][1]));
            mx1 = fmaxf(mx1, fmaxf(s[t][2], s[t][3]));
        }
        mx0 = fmaxf(mx0, __shfl_xor_sync(0xffffffffu, mx0, 1));
        mx0 = fmaxf(mx0, __shfl_xor_sync(0xffffffffu, mx0, 2));
        mx1 = fmaxf(mx1, __shfl_xor_sync(0xffffffffu, mx1, 1));
        mx1 = fmaxf(mx1, __shfl_xor_sync(0xffffffffu, mx1, 2));
        float mn0 = fmaxf(mc0, mx0), mn1 = fmaxf(mc1, mx1);
        float sc0 = exp2f(mc0 - mn0), sc1 = exp2f(mc1 - mn1);
        mc0 = mn0; mc1 = mn1;

#pragma unroll
        for (int t = 0; t < 8; t++) {
            o[t][0] *= sc0; o[t][1] *= sc0;
            o[t][2] *= sc1; o[t][3] *= sc1;
        }
        os[0] *= sc0; os[1] *= sc0; os[2] *= sc1; os[3] *= sc1;

#pragma unroll
        for (int kt = 0; kt < 8; kt++) {
            uint32_t pa[4];
            pa[0] = ex2h2(cvt2h(s[2 * kt][0] - mn0,     s[2 * kt][1] - mn0));
            pa[1] = ex2h2(cvt2h(s[2 * kt][2] - mn1,     s[2 * kt][3] - mn1));
            pa[2] = ex2h2(cvt2h(s[2 * kt + 1][0] - mn0, s[2 * kt + 1][1] - mn0));
            pa[3] = ex2h2(cvt2h(s[2 * kt + 1][2] - mn1, s[2 * kt + 1][3] - mn1));
            mma16816h(os, pa, ONES_H2, ONES_H2);
#pragma unroll
            for (int np = 0; np < 4; np++) {
                int brow = np * 16 + ((g >> 1) << 3) + rr;
                uint32_t off = swz16(brow, kt * 2 + (g & 1));
                uint32_t x0, x1, x2, x3;
                ldsm4(x0, x1, x2, x3, sb + OFF_X + off);
                mma16816h(o[2 * np],     pa, x0, x1);
                mma16816h(o[2 * np + 1], pa, x2, x3);
            }
        }
    }

    {
        int q = lane >> 2;
        int cb = (lane & 3) * 2;
        int r_lo = row0 + m0 + q;
        int r_hi = r_lo + 8;
        float* olo = g_Opart[half] + (size_t)r_lo * DIM;
        float* ohi = g_Opart[half] + (size_t)r_hi * DIM;
#pragma unroll
        for (int t = 0; t < 8; t++) {
            olo[t * 8 + cb]     = o[t][0];
            olo[t * 8 + cb + 1] = o[t][1];
            ohi[t * 8 + cb]     = o[t][2];
            ohi[t * 8 + cb + 1] = o[t][3];
        }
        if ((lane & 3) == 0) {
            g_mpart[half][r_lo] = mc0; g_mpart[half][r_hi] = mc1;
            g_lpart[half][r_lo] = os[0]; g_lpart[half][r_hi] = os[2];
        }
    }
}

// ---------------- combine (log2-domain m) ----------------
__global__ __launch_bounds__(256) void combine_kernel(float* __restrict__ out) {
    int idx = blockIdx.x * 256 + threadIdx.x;
    int row = idx >> 6;
    int c = idx & 63;
    float m0 = g_mpart[0][row], m1 = g_mpart[1][row];
    float M = fmaxf(m0, m1);
    float w0 = exp2f(m0 - M), w1 = exp2f(m1 - M);
    float inv = 1.0f / (g_lpart[0][row] * w0 + g_lpart[1][row] * w1);
    out[(size_t)row * DIM + c] =
        (g_Opart[0][(size_t)row * DIM + c] * w0 + g_Opart[1][(size_t)row * DIM + c] * w1) * inv;
}

extern "C" void kernel_launch(void* const* d_in, const int* in_sizes, int n_in,
                              void* d_out, int out_size) {
    const float* x = (const float*)d_in[0];
    const float* R = (const float*)d_in[1];
    const float* E = (const float*)d_in[2];
    float* out = (float*)d_out;

    cudaFuncSetAttribute(proj_tc, cudaFuncAttributeMaxDynamicSharedMemorySize, PT_SMEM);
    proj_tc<<<N_TOK / 64, 128, PT_SMEM>>>(x, R, E);

    cudaFuncSetAttribute(attn_kernel, cudaFuncAttributeMaxDynamicSharedMemorySize, SMEM_TOTAL);
    attn_kernel<<<(N_TOK / BM) * 2, 128, SMEM_TOTAL>>>();

    combine_kernel<<<(N_TOK * DIM) / 256, 256>>>(out);
}